// round 6
// baseline (speedup 1.0000x reference)
#include <cuda_runtime.h>
#include <cuda_fp16.h>
#include <math.h>

// ProbSparseAttention: B=2,H=8,L=4096,D=64, num_keys=num_queries=45
#define BB 2
#define HH 8
#define LL 4096
#define DD 64
#define BH (BB*HH)
#define NK 45
#define NQ 45
#define NSPLIT 16
#define CK 256            // keys per attention chunk
#define KP 260            // Kt row stride in floats (KP/4=65)
#define VP 68             // Vs row stride in floats
#define NEGINF (-1e30f)
#define NCAND 512
#define MARGIN 0.06f

// ---------------- scratch ----------------
__device__ uint4 g_kh4[BH * LL * DD / 8];    // fp16 copy of K (16B-aligned)
__device__ float g_sparsity[BH * LL];
__device__ int   g_cand[BH * NCAND];
__device__ int   g_ncand[BH];
__device__ int   g_qidx[BH * NQ];
__device__ float g_pm[BH * NQ * NSPLIT];
__device__ float g_pl[BH * NQ * NSPLIT];
__device__ float g_pacc[BH * NQ * NSPLIT * DD];
__device__ float g_csum[BH * 64 * DD];
__device__ float g_coff[BH * 64 * DD];

// ================= K1: convert K->fp16  +  csum_part (fused, independent) ==========
__global__ void k_conv_csum(const float* __restrict__ key, const float* __restrict__ val) {
    int bid = blockIdx.x, tid = threadIdx.x;
    if (bid < 2048) {
        long idx = (long)bid * 256 + tid;      // uint4 index, 8 halves each
        const float4* kf = (const float4*)key + idx * 2;
        float4 a = kf[0], b = kf[1];
        __half2 h0 = __floats2half2_rn(a.x, a.y);
        __half2 h1 = __floats2half2_rn(a.z, a.w);
        __half2 h2 = __floats2half2_rn(b.x, b.y);
        __half2 h3 = __floats2half2_rn(b.z, b.w);
        uint4 o;
        o.x = *(unsigned*)&h0; o.y = *(unsigned*)&h1;
        o.z = *(unsigned*)&h2; o.w = *(unsigned*)&h3;
        g_kh4[idx] = o;
    } else {
        int id = bid - 2048;
        int bh = id >> 4, cg = id & 15;
        int c = cg * 4 + (tid >> 6), d = tid & 63;
        const float* p = val + ((long)bh * LL + c * 64) * DD + d;
        float s = 0.f;
#pragma unroll 16
        for (int r = 0; r < 64; r++) s += p[r * DD];
        g_csum[(bh * 64 + c) * DD + d] = s;
    }
}

// ================= K2: approx sparsity with fp16 K =================
// One warp per query; 4 keys per iteration, 8 lanes coop-read each 128B fp16 row.
__global__ void k_sparsity(const float* __restrict__ q,
                           const int* __restrict__ kidx) {
    __shared__ __align__(16) float qs[8][DD];
    int w = threadIdx.x >> 5, lane = threadIdx.x & 31;
    int bh = blockIdx.x >> 9;
    int qrow = ((blockIdx.x & 511) << 3) + w;
    int g = lane >> 3, sub = lane & 7;

    float2 qv = ((const float2*)q)[((long)bh * LL + qrow) * 32 + lane];
    ((float2*)qs[w])[lane] = qv;
    __syncwarp();
    const float* qp = qs[w] + 8 * sub;
    float q0 = qp[0], q1 = qp[1], q2 = qp[2], q3 = qp[3];
    float q4 = qp[4], q5 = qp[5], q6 = qp[6], q7 = qp[7];

    const uint4* kh = g_kh4 + ((long)bh * LL) * 8;   // 8 uint4 per row
    const int* krow_idx = kidx + qrow * NK;

    float m = NEGINF, ssum = 0.f;
#pragma unroll
    for (int it = 0; it < 12; it++) {
        int j = it * 4 + g;
        int ki = (j < NK) ? krow_idx[j] : 0;
        uint4 kv = kh[(long)ki * 8 + sub];
        float2 f0 = __half22float2(*(__half2*)&kv.x);
        float2 f1 = __half22float2(*(__half2*)&kv.y);
        float2 f2 = __half22float2(*(__half2*)&kv.z);
        float2 f3 = __half22float2(*(__half2*)&kv.w);
        float s = q0 * f0.x + q1 * f0.y + q2 * f1.x + q3 * f1.y
                + q4 * f2.x + q5 * f2.y + q6 * f3.x + q7 * f3.y;
        s += __shfl_xor_sync(0xffffffffu, s, 4);
        s += __shfl_xor_sync(0xffffffffu, s, 2);
        s += __shfl_xor_sync(0xffffffffu, s, 1);
        if (sub == 0 && j < NK) { m = fmaxf(m, s); ssum += s; }
    }
    m = fmaxf(m, __shfl_xor_sync(0xffffffffu, m, 8));
    m = fmaxf(m, __shfl_xor_sync(0xffffffffu, m, 16));
    ssum += __shfl_xor_sync(0xffffffffu, ssum, 8);
    ssum += __shfl_xor_sync(0xffffffffu, ssum, 16);
    if (lane == 0)
        g_sparsity[bh * LL + qrow] = m - ssum * (1.0f / LL);
}

// ================= K3: radix threshold + margin candidates  +  csum_scan ==========
__global__ void k_topk_scan() {
    int bid = blockIdx.x, tid = threadIdx.x;
    if (bid >= BH) {                    // csum_scan part
        if (tid < 64) {
            int bh = bid - BH, d = tid;
            float run = 0.f;
#pragma unroll 8
            for (int c = 0; c < 64; c++) {
                int i = (bh * 64 + c) * DD + d;
                float t = g_csum[i];
                g_coff[i] = run;
                run += t;
            }
        }
        return;
    }
    __shared__ unsigned us[LL];
    __shared__ int hist[256];
    __shared__ unsigned sprefix;
    __shared__ int sb_need, s_nc;
    int bh = bid;

    for (int i = tid; i < LL; i += 256) {
        unsigned b = __float_as_uint(g_sparsity[bh * LL + i]);
        us[i] = (b & 0x80000000u) ? ~b : (b | 0x80000000u);
    }
    if (tid == 0) { sb_need = NQ; sprefix = 0; s_nc = 0; }
    __syncthreads();

    for (int pass = 0; pass < 4; pass++) {
        int shift = 24 - 8 * pass;
        hist[tid] = 0;
        __syncthreads();
        unsigned pfx = sprefix;
        for (int i = tid; i < LL; i += 256) {
            unsigned u = us[i];
            if (pass == 0 || (u >> (shift + 8)) == pfx)
                atomicAdd(&hist[(u >> shift) & 255], 1);
        }
        __syncthreads();
        if (tid == 0) {
            int need = sb_need, c = 0, b;
            for (b = 255; b >= 0; b--) {
                if (c + hist[b] >= need) break;
                c += hist[b];
            }
            sprefix = (pfx << 8) | (unsigned)b;
            sb_need = need - c;
        }
        __syncthreads();
    }
    unsigned T = sprefix;
    unsigned bb = (T >= 0x80000000u) ? (T & 0x7fffffffu) : ~T;
    float thresh = __uint_as_float(bb) - MARGIN;

    for (int i = tid; i < LL; i += 256) {
        if (g_sparsity[bh * LL + i] >= thresh) {
            int p = atomicAdd(&s_nc, 1);
            if (p < NCAND) g_cand[bh * NCAND + p] = i;
        }
    }
    __syncthreads();
    if (tid == 0) g_ncand[bh] = min(s_nc, NCAND);
}

// ================= K4: exact fp32 sparsity for candidates, exact top-45 ==========
__global__ void k_exact(const float* __restrict__ q,
                        const float* __restrict__ key,
                        const int* __restrict__ kidx) {
    __shared__ __align__(16) float qsm[8][DD];   // declared first: 16B-aligned (float4 casts)
    __shared__ __align__(16) float ev[NCAND];
    __shared__ int eidx[NCAND];
    __shared__ int sel[NQ];
    int bh = blockIdx.x, tid = threadIdx.x;
    int w = tid >> 5, lane = tid & 31;

    int nc = g_ncand[bh];
    for (int i = tid; i < NCAND; i += 256) { ev[i] = -1e38f; eidx[i] = 0x7fffffff; }
    __syncthreads();

    for (int c = w; c < nc; c += 8) {
        int qrow = g_cand[bh * NCAND + c];
        float2 qv = ((const float2*)q)[((long)bh * LL + qrow) * 32 + lane];
        ((float2*)qsm[w])[lane] = qv;
        __syncwarp();
        const float4* qs4 = (const float4*)qsm[w];
        const float4* k4 = (const float4*)key;
        int i0 = kidx[qrow * NK + lane];
        bool has1 = (lane < NK - 32);
        int i1 = has1 ? kidx[qrow * NK + lane + 32] : 0;
        const float4* kr0 = k4 + ((long)bh * LL + i0) * 16;
        const float4* kr1 = k4 + ((long)bh * LL + i1) * 16;
        float s0 = 0.f, s1 = 0.f;
#pragma unroll
        for (int t = 0; t < 16; t++) {
            float4 qq = qs4[t];
            float4 a = kr0[t];
            s0 += qq.x * a.x + qq.y * a.y + qq.z * a.z + qq.w * a.w;
            float4 b = kr1[t];
            s1 += qq.x * b.x + qq.y * b.y + qq.z * b.z + qq.w * b.w;
        }
        float m = has1 ? fmaxf(s0, s1) : s0;
        float ssum = s0 + (has1 ? s1 : 0.f);
#pragma unroll
        for (int o = 16; o > 0; o >>= 1) {
            m = fmaxf(m, __shfl_xor_sync(0xffffffffu, m, o));
            ssum += __shfl_xor_sync(0xffffffffu, ssum, o);
        }
        if (lane == 0) { ev[c] = m - ssum * (1.0f / LL); eidx[c] = qrow; }
        __syncwarp();
    }
    __syncthreads();

    // warp 0: exact top-45 by (value desc, index asc)
    if (w == 0) {
        unsigned long long kk[NCAND / 32];
#pragma unroll
        for (int t = 0; t < NCAND / 32; t++) {
            int c = lane + 32 * t;
            unsigned b = __float_as_uint(ev[c]);
            unsigned u = (b & 0x80000000u) ? ~b : (b | 0x80000000u);
            kk[t] = ((unsigned long long)u << 32) | (unsigned)(~eidx[c]);
        }
        for (int it = 0; it < NQ; it++) {
            unsigned long long lb = 0; int lt = -1;
#pragma unroll
            for (int t = 0; t < NCAND / 32; t++)
                if (kk[t] > lb) { lb = kk[t]; lt = t; }
            unsigned long long gb = lb;
#pragma unroll
            for (int o = 16; o > 0; o >>= 1) {
                unsigned long long other = __shfl_xor_sync(0xffffffffu, gb, o);
                if (other > gb) gb = other;
            }
            if (lt >= 0 && lb == gb) kk[lt] = 0;   // winner clears (keys unique)
            if (lane == 0) sel[it] = (int)(~(unsigned)(gb & 0xffffffffu));
        }
        if (lane == 0) {
            for (int a2 = 1; a2 < NQ; a2++) {      // sort ascending (order-free)
                int v = sel[a2], b2 = a2 - 1;
                while (b2 >= 0 && sel[b2] > v) { sel[b2 + 1] = sel[b2]; b2--; }
                sel[b2 + 1] = v;
            }
            for (int a2 = 0; a2 < NQ; a2++) g_qidx[bh * NQ + a2] = sel[a2];
        }
    }
}

// ================= K5: split-K attention (4 queries/warp)  +  csum_apply ==========
__global__ void __launch_bounds__(256, 1)
k_attn_apply(const float* __restrict__ q,
             const float* __restrict__ key,
             const float* __restrict__ val,
             float* __restrict__ out) {
    int bid = blockIdx.x, tid = threadIdx.x;
    if (bid >= 256) {                 // ---- csum_apply part ----
        int id = bid - 256;
        int bh = id >> 4, cg = id & 15;
        int c = cg * 4 + (tid >> 6), d = tid & 63;
        long base = ((long)bh * LL + c * 64) * DD + d;
        float run = g_coff[(bh * 64 + c) * DD + d];
#pragma unroll 16
        for (int r = 0; r < 64; r++) {
            run += val[base + r * DD];
            out[base + r * DD] = run;
        }
        return;
    }
    extern __shared__ float sm[];
    float* Kt = sm;                       // DD*KP
    float* Vs = Kt + DD * KP;             // CK*VP
    float* qs = Vs + CK * VP;             // NQ*DD
    float* ps = qs + NQ * DD;             // 32 * CK
    int* qis = (int*)(ps + 32 * CK);      // NQ

    int bh = bid >> 4, split = bid & 15;
    int w = tid >> 5, lane = tid & 31;
    int cs = split * CK;

    if (tid < NQ) qis[tid] = g_qidx[bh * NQ + tid];
    __syncthreads();

    for (int i = tid; i < NQ * DD / 4; i += 256) {
        int slot = i >> 4, d4 = i & 15;
        ((float4*)qs)[i] = ((const float4*)q)[((long)bh * LL + qis[slot]) * 16 + d4];
    }
    const float4* k4 = (const float4*)key + ((long)bh * LL + cs) * 16;
    const float4* v4 = (const float4*)val + ((long)bh * LL + cs) * 16;
#pragma unroll
    for (int it = 0; it < 16; it++) {
        int idx = tid + it * 256;
        int kk = idx >> 4, d4 = idx & 15;
        float4 a = k4[idx];
        Kt[(4 * d4 + 0) * KP + kk] = a.x;
        Kt[(4 * d4 + 1) * KP + kk] = a.y;
        Kt[(4 * d4 + 2) * KP + kk] = a.z;
        Kt[(4 * d4 + 3) * KP + kk] = a.w;
        *(float4*)(Vs + kk * VP + 4 * d4) = v4[idx];
    }
    __syncthreads();

    const float4* KtA = (const float4*)Kt;   // [d*65 + lane]

    for (int g = w; g < 12; g += 8) {        // 12 groups of 4 slots
        int kend[4], pidx[4], st[4];
        int kendM = 0;
#pragma unroll
        for (int t = 0; t < 4; t++) {
            int s = 4 * g + t;
            bool act = s < NQ;
            int qi = act ? qis[s] : 0;
            st[t] = act ? s : 0;
            pidx[t] = (bh * NQ + (act ? s : 0)) * NSPLIT + split;
            int ke = act ? min(CK, qi - cs + 1) : 0;
            if (ke < 0) ke = 0;
            if (!act) ke = 0;
            kend[t] = ke;
            if (act && ke == 0 && lane == 0) { g_pm[pidx[t]] = NEGINF; g_pl[pidx[t]] = 0.f; }
            kendM = max(kendM, ke);
        }
        if (kendM == 0) continue;
        bool do1 = (kendM > 128);

        float A0[4][4] = {}, A1[4][4] = {};
#pragma unroll
        for (int d4 = 0; d4 < 16; d4++) {
            float4 qv[4];
#pragma unroll
            for (int t = 0; t < 4; t++) qv[t] = ((const float4*)(qs + st[t] * DD))[d4];
#pragma unroll
            for (int dd = 0; dd < 4; dd++) {
                float4 kk = KtA[(4 * d4 + dd) * 65 + lane];
#pragma unroll
                for (int t = 0; t < 4; t++) {
                    float qa = (dd == 0) ? qv[t].x : (dd == 1) ? qv[t].y : (dd == 2) ? qv[t].z : qv[t].w;
                    A0[t][0] += qa * kk.x; A0[t][1] += qa * kk.y;
                    A0[t][2] += qa * kk.z; A0[t][3] += qa * kk.w;
                }
                if (do1) {
                    float4 kk1 = KtA[(4 * d4 + dd) * 65 + 32 + lane];
#pragma unroll
                    for (int t = 0; t < 4; t++) {
                        float qa = (dd == 0) ? qv[t].x : (dd == 1) ? qv[t].y : (dd == 2) ? qv[t].z : qv[t].w;
                        A1[t][0] += qa * kk1.x; A1[t][1] += qa * kk1.y;
                        A1[t][2] += qa * kk1.z; A1[t][3] += qa * kk1.w;
                    }
                }
            }
        }

        int kb = 4 * lane, kb1 = 128 + 4 * lane;
        float mo[4], lo[4];
#pragma unroll
        for (int t = 0; t < 4; t++) {
            mo[t] = NEGINF; lo[t] = 0.f;
            if (kend[t] == 0) continue;
            float sc[8];
#pragma unroll
            for (int u = 0; u < 4; u++) sc[u] = (kb + u < kend[t]) ? A0[t][u] * 0.125f : NEGINF;
#pragma unroll
            for (int u = 0; u < 4; u++) sc[4 + u] = (do1 && kb1 + u < kend[t]) ? A1[t][u] * 0.125f : NEGINF;
            float m = sc[0];
#pragma unroll
            for (int u = 1; u < 8; u++) m = fmaxf(m, sc[u]);
#pragma unroll
            for (int o = 16; o > 0; o >>= 1) m = fmaxf(m, __shfl_xor_sync(0xffffffffu, m, o));
            float pv[8], l = 0.f;
#pragma unroll
            for (int u = 0; u < 8; u++) {
                bool ok = (u < 4) ? (kb + u < kend[t]) : (do1 && kb1 + (u - 4) < kend[t]);
                pv[u] = ok ? __expf(sc[u] - m) : 0.f;
                l += pv[u];
            }
#pragma unroll
            for (int o = 16; o > 0; o >>= 1) l += __shfl_xor_sync(0xffffffffu, l, o);
            float* pst = ps + (w * 4 + t) * CK;
            *(float4*)(pst + kb) = make_float4(pv[0], pv[1], pv[2], pv[3]);
            if (do1) *(float4*)(pst + kb1) = make_float4(pv[4], pv[5], pv[6], pv[7]);
            mo[t] = m; lo[t] = l;
        }
        __syncwarp();

        // PV: even keys lanes 0-15, odd keys lanes 16-31; float4 over dims
        float4 acc[4];
#pragma unroll
        for (int t = 0; t < 4; t++) acc[t] = make_float4(0, 0, 0, 0);
        int half = lane >> 4, dl = lane & 15;
        const float* psb = ps + w * 4 * CK;
        for (int k = half; k < kendM; k += 2) {
            float4 vv = *(const float4*)(Vs + k * VP + 4 * dl);
#pragma unroll
            for (int t = 0; t < 4; t++) {
                float pk = psb[t * CK + k];
                acc[t].x += pk * vv.x; acc[t].y += pk * vv.y;
                acc[t].z += pk * vv.z; acc[t].w += pk * vv.w;
            }
        }
#pragma unroll
        for (int t = 0; t < 4; t++) {
            acc[t].x += __shfl_down_sync(0xffffffffu, acc[t].x, 16);
            acc[t].y += __shfl_down_sync(0xffffffffu, acc[t].y, 16);
            acc[t].z += __shfl_down_sync(0xffffffffu, acc[t].z, 16);
            acc[t].w += __shfl_down_sync(0xffffffffu, acc[t].w, 16);
        }
        if (lane < 16) {
#pragma unroll
            for (int t = 0; t < 4; t++)
                if (kend[t] > 0) ((float4*)(g_pacc + (long)pidx[t] * DD))[dl] = acc[t];
        }
        if (lane == 0) {
#pragma unroll
            for (int t = 0; t < 4; t++)
                if (kend[t] > 0) { g_pm[pidx[t]] = mo[t]; g_pl[pidx[t]] = lo[t]; }
        }
        __syncwarp();
    }
}

// ================= K6: combine split-K partials, scatter into output ==========
__global__ void k_combine(float* __restrict__ out) {
    int slot = blockIdx.x, bh = blockIdx.y, d = threadIdx.x;
    int base = (bh * NQ + slot) * NSPLIT;
    float M = NEGINF;
#pragma unroll
    for (int s = 0; s < NSPLIT; s++) M = fmaxf(M, g_pm[base + s]);
    float Lsum = 0.f, acc = 0.f;
#pragma unroll
    for (int s = 0; s < NSPLIT; s++) {
        float l = g_pl[base + s];
        if (l > 0.f) {
            float sc = __expf(g_pm[base + s] - M);
            Lsum += l * sc;
            acc += sc * g_pacc[(long)(base + s) * DD + d];
        }
    }
    int qi = g_qidx[bh * NQ + slot];
    out[((long)bh * LL + qi) * DD + d] = acc / Lsum;
}

// ---------------- launch ----------------
extern "C" void kernel_launch(void* const* d_in, const int* in_sizes, int n_in,
                              void* d_out, int out_size) {
    const float* q = (const float*)d_in[0];
    const float* k = (const float*)d_in[1];
    const float* v = (const float*)d_in[2];
    const int* kidx = (const int*)d_in[3];
    float* out = (float*)d_out;
    (void)in_sizes; (void)n_in; (void)out_size;

    int smem_attn = (DD * KP + CK * VP + NQ * DD + 32 * CK) * 4 + NQ * 4 + 16;
    cudaFuncSetAttribute(k_attn_apply, cudaFuncAttributeMaxDynamicSharedMemorySize, smem_attn);

    k_conv_csum<<<2048 + 256, 256>>>(k, v);
    k_sparsity<<<BH * (LL / 8), 256>>>(q, kidx);
    k_topk_scan<<<2 * BH, 256>>>();
    k_exact<<<BH, 256>>>(q, k, kidx);
    k_attn_apply<<<512, 256, smem_attn>>>(q, k, v, out);
    k_combine<<<dim3(NQ, BH), 64>>>(out);
}

// round 9
// speedup vs baseline: 1.0533x; 1.0533x over previous
#include <cuda_runtime.h>
#include <cuda_fp16.h>
#include <math.h>

// ProbSparseAttention: B=2,H=8,L=4096,D=64, num_keys=num_queries=45
#define BB 2
#define HH 8
#define LL 4096
#define DD 64
#define BH (BB*HH)
#define NK 45
#define NQ 45
#define NSPLIT 16
#define CK 256            // keys per attention chunk
#define KP 260            // Kt row stride in floats (KP/4=65)
#define VP 68             // Vs row stride in floats
#define NEGINF (-1e30f)
#define NCAND 1024
#define MARGIN 0.06f

// ---------------- scratch ----------------
__device__ uint4 g_kh4[BH * LL * DD / 8];    // fp16 copy of K (16B-aligned)
__device__ float g_sparsity[BH * LL];
__device__ int   g_cand[BH * NCAND];
__device__ float g_ev[BH * NCAND];
__device__ int   g_ncand[BH];
__device__ int   g_qidx[BH * NQ];
__device__ float g_pm[BH * NQ * NSPLIT];
__device__ float g_pl[BH * NQ * NSPLIT];
__device__ float g_pacc[BH * NQ * NSPLIT * DD];
__device__ float g_csum[BH * 64 * DD];
__device__ float g_coff[BH * 64 * DD];

// ================= K1: convert K->fp16  +  csum_part (fused, independent) ==========
__global__ void k_conv_csum(const float* __restrict__ key, const float* __restrict__ val) {
    int bid = blockIdx.x, tid = threadIdx.x;
    if (bid < 2048) {
        long idx = (long)bid * 256 + tid;      // uint4 index, 8 halves each
        const float4* kf = (const float4*)key + idx * 2;
        float4 a = kf[0], b = kf[1];
        __half2 h0 = __floats2half2_rn(a.x, a.y);
        __half2 h1 = __floats2half2_rn(a.z, a.w);
        __half2 h2 = __floats2half2_rn(b.x, b.y);
        __half2 h3 = __floats2half2_rn(b.z, b.w);
        uint4 o;
        o.x = *(unsigned*)&h0; o.y = *(unsigned*)&h1;
        o.z = *(unsigned*)&h2; o.w = *(unsigned*)&h3;
        g_kh4[idx] = o;
    } else {
        int id = bid - 2048;
        int bh = id >> 4, cg = id & 15;
        int c = cg * 4 + (tid >> 6), d = tid & 63;
        const float* p = val + ((long)bh * LL + c * 64) * DD + d;
        float s = 0.f;
#pragma unroll 16
        for (int r = 0; r < 64; r++) s += p[r * DD];
        g_csum[(bh * 64 + c) * DD + d] = s;
    }
}

// ================= K2: approx sparsity with fp16 K =================
__global__ void k_sparsity(const float* __restrict__ q,
                           const int* __restrict__ kidx) {
    __shared__ __align__(16) float qs[8][DD];
    int w = threadIdx.x >> 5, lane = threadIdx.x & 31;
    int bh = blockIdx.x >> 9;
    int qrow = ((blockIdx.x & 511) << 3) + w;
    int g = lane >> 3, sub = lane & 7;

    float2 qv = ((const float2*)q)[((long)bh * LL + qrow) * 32 + lane];
    ((float2*)qs[w])[lane] = qv;
    __syncwarp();
    const float* qp = qs[w] + 8 * sub;
    float q0 = qp[0], q1 = qp[1], q2 = qp[2], q3 = qp[3];
    float q4 = qp[4], q5 = qp[5], q6 = qp[6], q7 = qp[7];

    const uint4* kh = g_kh4 + ((long)bh * LL) * 8;   // 8 uint4 per row
    const int* krow_idx = kidx + qrow * NK;

    float m = NEGINF, ssum = 0.f;
#pragma unroll
    for (int it = 0; it < 12; it++) {
        int j = it * 4 + g;
        int ki = (j < NK) ? krow_idx[j] : 0;
        uint4 kv = kh[(long)ki * 8 + sub];
        float2 f0 = __half22float2(*(__half2*)&kv.x);
        float2 f1 = __half22float2(*(__half2*)&kv.y);
        float2 f2 = __half22float2(*(__half2*)&kv.z);
        float2 f3 = __half22float2(*(__half2*)&kv.w);
        float s = q0 * f0.x + q1 * f0.y + q2 * f1.x + q3 * f1.y
                + q4 * f2.x + q5 * f2.y + q6 * f3.x + q7 * f3.y;
        s += __shfl_xor_sync(0xffffffffu, s, 4);
        s += __shfl_xor_sync(0xffffffffu, s, 2);
        s += __shfl_xor_sync(0xffffffffu, s, 1);
        if (sub == 0 && j < NK) { m = fmaxf(m, s); ssum += s; }
    }
    m = fmaxf(m, __shfl_xor_sync(0xffffffffu, m, 8));
    m = fmaxf(m, __shfl_xor_sync(0xffffffffu, m, 16));
    ssum += __shfl_xor_sync(0xffffffffu, ssum, 8);
    ssum += __shfl_xor_sync(0xffffffffu, ssum, 16);
    if (lane == 0)
        g_sparsity[bh * LL + qrow] = m - ssum * (1.0f / LL);
}

// ================= K3: radix threshold + margin candidates  +  csum_scan ==========
__global__ void k_topk_scan() {
    int bid = blockIdx.x, tid = threadIdx.x;
    if (bid >= BH) {                    // csum_scan part
        if (tid < 64) {
            int bh = bid - BH, d = tid;
            float run = 0.f;
#pragma unroll 8
            for (int c = 0; c < 64; c++) {
                int i = (bh * 64 + c) * DD + d;
                float t = g_csum[i];
                g_coff[i] = run;
                run += t;
            }
        }
        return;
    }
    __shared__ unsigned us[LL];
    __shared__ int hist[256];
    __shared__ unsigned sprefix;
    __shared__ int sb_need, s_nc;
    int bh = bid;

    for (int i = tid; i < LL; i += 256) {
        unsigned b = __float_as_uint(g_sparsity[bh * LL + i]);
        us[i] = (b & 0x80000000u) ? ~b : (b | 0x80000000u);
    }
    if (tid == 0) { sb_need = NQ; sprefix = 0; s_nc = 0; }
    __syncthreads();

    for (int pass = 0; pass < 4; pass++) {
        int shift = 24 - 8 * pass;
        hist[tid] = 0;
        __syncthreads();
        unsigned pfx = sprefix;
        for (int i = tid; i < LL; i += 256) {
            unsigned u = us[i];
            if (pass == 0 || (u >> (shift + 8)) == pfx)
                atomicAdd(&hist[(u >> shift) & 255], 1);
        }
        __syncthreads();
        if (tid == 0) {
            int need = sb_need, c = 0, b;
            for (b = 255; b >= 0; b--) {
                if (c + hist[b] >= need) break;
                c += hist[b];
            }
            sprefix = (pfx << 8) | (unsigned)b;
            sb_need = need - c;
        }
        __syncthreads();
    }
    unsigned T = sprefix;
    unsigned bb = (T >= 0x80000000u) ? (T & 0x7fffffffu) : ~T;
    float thresh = __uint_as_float(bb) - MARGIN;

    for (int i = tid; i < LL; i += 256) {
        if (g_sparsity[bh * LL + i] >= thresh) {
            int p = atomicAdd(&s_nc, 1);
            if (p < NCAND) g_cand[bh * NCAND + p] = i;
        }
    }
    __syncthreads();
    if (tid == 0) g_ncand[bh] = min(s_nc, NCAND);
}

// ================= K4: exact fp32 sparsity for candidates (wide grid) ==========
// grid = BH*16 blocks, 8 warps each: candidate c = part*8 + w, stride 128.
__global__ void k_exact_score(const float* __restrict__ q,
                              const float* __restrict__ key,
                              const int* __restrict__ kidx) {
    __shared__ __align__(16) float qsm[8][DD];
    int bh = blockIdx.x >> 4, part = blockIdx.x & 15;
    int tid = threadIdx.x, w = tid >> 5, lane = tid & 31;
    int nc = g_ncand[bh];

    for (int c = part * 8 + w; c < nc; c += 128) {
        int qrow = g_cand[bh * NCAND + c];
        float2 qv = ((const float2*)q)[((long)bh * LL + qrow) * 32 + lane];
        ((float2*)qsm[w])[lane] = qv;
        __syncwarp();
        const float4* qs4 = (const float4*)qsm[w];
        const float4* k4 = (const float4*)key;
        int i0 = kidx[qrow * NK + lane];
        bool has1 = (lane < NK - 32);
        int i1 = has1 ? kidx[qrow * NK + lane + 32] : 0;
        const float4* kr0 = k4 + ((long)bh * LL + i0) * 16;
        const float4* kr1 = k4 + ((long)bh * LL + i1) * 16;
        float s0 = 0.f, s1 = 0.f;
#pragma unroll
        for (int t = 0; t < 16; t++) {
            float4 qq = qs4[t];
            float4 a = kr0[t];
            s0 += qq.x * a.x + qq.y * a.y + qq.z * a.z + qq.w * a.w;
            float4 b = kr1[t];
            s1 += qq.x * b.x + qq.y * b.y + qq.z * b.z + qq.w * b.w;
        }
        float m = has1 ? fmaxf(s0, s1) : s0;
        float ssum = s0 + (has1 ? s1 : 0.f);
#pragma unroll
        for (int o = 16; o > 0; o >>= 1) {
            m = fmaxf(m, __shfl_xor_sync(0xffffffffu, m, o));
            ssum += __shfl_xor_sync(0xffffffffu, ssum, o);
        }
        if (lane == 0) g_ev[bh * NCAND + c] = m - ssum * (1.0f / LL);
        __syncwarp();
    }
}

// ================= K5: exact top-45 selection (block-parallel tournament) ==========
// grid = BH, block = 512. Candidates packed u64 (ordered-float<<32 | ~idx) in regs.
__global__ void __launch_bounds__(512, 1)
k_select() {
    __shared__ unsigned long long partial[16];
    __shared__ unsigned long long swin;
    __shared__ int sel[NQ];
    int bh = blockIdx.x, tid = threadIdx.x;
    int w = tid >> 5, lane = tid & 31;
    int nc = g_ncand[bh];

    unsigned long long key0 = 0, key1 = 0;
    if (tid < nc) {
        unsigned b = __float_as_uint(g_ev[bh * NCAND + tid]);
        unsigned u = (b & 0x80000000u) ? ~b : (b | 0x80000000u);
        key0 = ((unsigned long long)u << 32) | (unsigned)(~g_cand[bh * NCAND + tid]);
    }
    if (tid + 512 < nc) {
        unsigned b = __float_as_uint(g_ev[bh * NCAND + tid + 512]);
        unsigned u = (b & 0x80000000u) ? ~b : (b | 0x80000000u);
        key1 = ((unsigned long long)u << 32) | (unsigned)(~g_cand[bh * NCAND + tid + 512]);
    }

    for (int it = 0; it < NQ; it++) {
        unsigned long long loc = key0 > key1 ? key0 : key1;
#pragma unroll
        for (int o = 16; o > 0; o >>= 1) {
            unsigned long long v = __shfl_xor_sync(0xffffffffu, loc, o);
            if (v > loc) loc = v;
        }
        if (lane == 0) partial[w] = loc;
        __syncthreads();
        if (w == 0) {
            unsigned long long v = (lane < 16) ? partial[lane] : 0;
#pragma unroll
            for (int o = 8; o > 0; o >>= 1) {
                unsigned long long x = __shfl_xor_sync(0xffffffffu, v, o);
                if (x > v) v = x;
            }
            if (lane == 0) {
                swin = v;
                sel[it] = (int)(~(unsigned)(v & 0xffffffffu));
            }
        }
        __syncthreads();
        unsigned long long win = swin;
        if (key0 == win) key0 = 0;     // keys unique (idx embedded)
        if (key1 == win) key1 = 0;
        __syncthreads();
    }
    if (tid == 0) {
        for (int a2 = 1; a2 < NQ; a2++) {      // sort ascending (order-free)
            int v = sel[a2], b2 = a2 - 1;
            while (b2 >= 0 && sel[b2] > v) { sel[b2 + 1] = sel[b2]; b2--; }
            sel[b2 + 1] = v;
        }
        for (int a2 = 0; a2 < NQ; a2++) g_qidx[bh * NQ + a2] = sel[a2];
    }
}

// ================= K6: split-K attention (4 queries/warp)  +  csum_apply ==========
__global__ void __launch_bounds__(256, 1)
k_attn_apply(const float* __restrict__ q,
             const float* __restrict__ key,
             const float* __restrict__ val,
             float* __restrict__ out) {
    int bid = blockIdx.x, tid = threadIdx.x;
    if (bid >= 256) {                 // ---- csum_apply part ----
        int id = bid - 256;
        int bh = id >> 4, cg = id & 15;
        int c = cg * 4 + (tid >> 6), d = tid & 63;
        long base = ((long)bh * LL + c * 64) * DD + d;
        float run = g_coff[(bh * 64 + c) * DD + d];
#pragma unroll 16
        for (int r = 0; r < 64; r++) {
            run += val[base + r * DD];
            out[base + r * DD] = run;
        }
        return;
    }
    extern __shared__ float sm[];
    float* Kt = sm;                       // DD*KP
    float* Vs = Kt + DD * KP;             // CK*VP
    float* qs = Vs + CK * VP;             // NQ*DD
    float* ps = qs + NQ * DD;             // 32 * CK
    int* qis = (int*)(ps + 32 * CK);      // NQ

    int bh = bid >> 4, split = bid & 15;
    int w = tid >> 5, lane = tid & 31;
    int cs = split * CK;

    if (tid < NQ) qis[tid] = g_qidx[bh * NQ + tid];
    __syncthreads();

    for (int i = tid; i < NQ * DD / 4; i += 256) {
        int slot = i >> 4, d4 = i & 15;
        ((float4*)qs)[i] = ((const float4*)q)[((long)bh * LL + qis[slot]) * 16 + d4];
    }
    const float4* k4 = (const float4*)key + ((long)bh * LL + cs) * 16;
    const float4* v4 = (const float4*)val + ((long)bh * LL + cs) * 16;
#pragma unroll
    for (int it = 0; it < 16; it++) {
        int idx = tid + it * 256;
        int kk = idx >> 4, d4 = idx & 15;
        float4 a = k4[idx];
        Kt[(4 * d4 + 0) * KP + kk] = a.x;
        Kt[(4 * d4 + 1) * KP + kk] = a.y;
        Kt[(4 * d4 + 2) * KP + kk] = a.z;
        Kt[(4 * d4 + 3) * KP + kk] = a.w;
        *(float4*)(Vs + kk * VP + 4 * d4) = v4[idx];
    }
    __syncthreads();

    const float4* KtA = (const float4*)Kt;   // [d*65 + lane]

    for (int g = w; g < 12; g += 8) {        // 12 groups of 4 slots
        int kend[4], pidx[4], st[4];
        int kendM = 0;
#pragma unroll
        for (int t = 0; t < 4; t++) {
            int s = 4 * g + t;
            bool act = s < NQ;
            int qi = act ? qis[s] : 0;
            st[t] = act ? s : 0;
            pidx[t] = (bh * NQ + (act ? s : 0)) * NSPLIT + split;
            int ke = act ? min(CK, qi - cs + 1) : 0;
            if (ke < 0) ke = 0;
            if (!act) ke = 0;
            kend[t] = ke;
            if (act && ke == 0 && lane == 0) { g_pm[pidx[t]] = NEGINF; g_pl[pidx[t]] = 0.f; }
            kendM = max(kendM, ke);
        }
        if (kendM == 0) continue;
        bool do1 = (kendM > 128);

        float A0[4][4] = {}, A1[4][4] = {};
#pragma unroll
        for (int d4 = 0; d4 < 16; d4++) {
            float4 qv[4];
#pragma unroll
            for (int t = 0; t < 4; t++) qv[t] = ((const float4*)(qs + st[t] * DD))[d4];
#pragma unroll
            for (int dd = 0; dd < 4; dd++) {
                float4 kk = KtA[(4 * d4 + dd) * 65 + lane];
#pragma unroll
                for (int t = 0; t < 4; t++) {
                    float qa = (dd == 0) ? qv[t].x : (dd == 1) ? qv[t].y : (dd == 2) ? qv[t].z : qv[t].w;
                    A0[t][0] += qa * kk.x; A0[t][1] += qa * kk.y;
                    A0[t][2] += qa * kk.z; A0[t][3] += qa * kk.w;
                }
                if (do1) {
                    float4 kk1 = KtA[(4 * d4 + dd) * 65 + 32 + lane];
#pragma unroll
                    for (int t = 0; t < 4; t++) {
                        float qa = (dd == 0) ? qv[t].x : (dd == 1) ? qv[t].y : (dd == 2) ? qv[t].z : qv[t].w;
                        A1[t][0] += qa * kk1.x; A1[t][1] += qa * kk1.y;
                        A1[t][2] += qa * kk1.z; A1[t][3] += qa * kk1.w;
                    }
                }
            }
        }

        int kb = 4 * lane, kb1 = 128 + 4 * lane;
        float mo[4], lo[4];
#pragma unroll
        for (int t = 0; t < 4; t++) {
            mo[t] = NEGINF; lo[t] = 0.f;
            if (kend[t] == 0) continue;
            float sc[8];
#pragma unroll
            for (int u = 0; u < 4; u++) sc[u] = (kb + u < kend[t]) ? A0[t][u] * 0.125f : NEGINF;
#pragma unroll
            for (int u = 0; u < 4; u++) sc[4 + u] = (do1 && kb1 + u < kend[t]) ? A1[t][u] * 0.125f : NEGINF;
            float m = sc[0];
#pragma unroll
            for (int u = 1; u < 8; u++) m = fmaxf(m, sc[u]);
#pragma unroll
            for (int o = 16; o > 0; o >>= 1) m = fmaxf(m, __shfl_xor_sync(0xffffffffu, m, o));
            float pv[8], l = 0.f;
#pragma unroll
            for (int u = 0; u < 8; u++) {
                bool ok = (u < 4) ? (kb + u < kend[t]) : (do1 && kb1 + (u - 4) < kend[t]);
                pv[u] = ok ? __expf(sc[u] - m) : 0.f;
                l += pv[u];
            }
#pragma unroll
            for (int o = 16; o > 0; o >>= 1) l += __shfl_xor_sync(0xffffffffu, l, o);
            float* pst = ps + (w * 4 + t) * CK;
            *(float4*)(pst + kb) = make_float4(pv[0], pv[1], pv[2], pv[3]);
            if (do1) *(float4*)(pst + kb1) = make_float4(pv[4], pv[5], pv[6], pv[7]);
            mo[t] = m; lo[t] = l;
        }
        __syncwarp();

        // PV: even keys lanes 0-15, odd keys lanes 16-31; float4 over dims
        float4 acc[4];
#pragma unroll
        for (int t = 0; t < 4; t++) acc[t] = make_float4(0, 0, 0, 0);
        int half = lane >> 4, dl = lane & 15;
        const float* psb = ps + w * 4 * CK;
        for (int k = half; k < kendM; k += 2) {
            float4 vv = *(const float4*)(Vs + k * VP + 4 * dl);
#pragma unroll
            for (int t = 0; t < 4; t++) {
                float pk = psb[t * CK + k];
                acc[t].x += pk * vv.x; acc[t].y += pk * vv.y;
                acc[t].z += pk * vv.z; acc[t].w += pk * vv.w;
            }
        }
#pragma unroll
        for (int t = 0; t < 4; t++) {
            acc[t].x += __shfl_down_sync(0xffffffffu, acc[t].x, 16);
            acc[t].y += __shfl_down_sync(0xffffffffu, acc[t].y, 16);
            acc[t].z += __shfl_down_sync(0xffffffffu, acc[t].z, 16);
            acc[t].w += __shfl_down_sync(0xffffffffu, acc[t].w, 16);
        }
        if (lane < 16) {
#pragma unroll
            for (int t = 0; t < 4; t++)
                if (kend[t] > 0) ((float4*)(g_pacc + (long)pidx[t] * DD))[dl] = acc[t];
        }
        if (lane == 0) {
#pragma unroll
            for (int t = 0; t < 4; t++)
                if (kend[t] > 0) { g_pm[pidx[t]] = mo[t]; g_pl[pidx[t]] = lo[t]; }
        }
        __syncwarp();
    }
}

// ================= K7: combine split-K partials, scatter into output ==========
__global__ void k_combine(float* __restrict__ out) {
    int slot = blockIdx.x, bh = blockIdx.y, d = threadIdx.x;
    int base = (bh * NQ + slot) * NSPLIT;
    float M = NEGINF;
#pragma unroll
    for (int s = 0; s < NSPLIT; s++) M = fmaxf(M, g_pm[base + s]);
    float Lsum = 0.f, acc = 0.f;
#pragma unroll
    for (int s = 0; s < NSPLIT; s++) {
        float l = g_pl[base + s];
        if (l > 0.f) {
            float sc = __expf(g_pm[base + s] - M);
            Lsum += l * sc;
            acc += sc * g_pacc[(long)(base + s) * DD + d];
        }
    }
    int qi = g_qidx[bh * NQ + slot];
    out[((long)bh * LL + qi) * DD + d] = acc / Lsum;
}

// ---------------- launch ----------------
extern "C" void kernel_launch(void* const* d_in, const int* in_sizes, int n_in,
                              void* d_out, int out_size) {
    const float* q = (const float*)d_in[0];
    const float* k = (const float*)d_in[1];
    const float* v = (const float*)d_in[2];
    const int* kidx = (const int*)d_in[3];
    float* out = (float*)d_out;
    (void)in_sizes; (void)n_in; (void)out_size;

    int smem_attn = (DD * KP + CK * VP + NQ * DD + 32 * CK) * 4 + NQ * 4 + 16;
    cudaFuncSetAttribute(k_attn_apply, cudaFuncAttributeMaxDynamicSharedMemorySize, smem_attn);

    k_conv_csum<<<2048 + 256, 256>>>(k, v);
    k_sparsity<<<BH * (LL / 8), 256>>>(q, kidx);
    k_topk_scan<<<2 * BH, 256>>>();
    k_exact_score<<<BH * 16, 256>>>(q, k, kidx);
    k_select<<<BH, 512>>>();
    k_attn_apply<<<512, 256, smem_attn>>>(q, k, v, out);
    k_combine<<<dim3(NQ, BH), 64>>>(out);
}